// round 1
// baseline (speedup 1.0000x reference)
#include <cuda_runtime.h>

// SimpleGRU: B=2048 sequences, T=2048 steps, H=32, scalar input.
// One warp per batch element; lane i owns hidden unit i and holds the
// three W_hh rows (r,z,n) for unit i as packed f32x2 pairs in registers.
// Per-step matvec = 48 fma.rn.f32x2. h broadcast via 128B shared buffer.

#define FULL_MASK 0xffffffffu

using u64 = unsigned long long;

__device__ __forceinline__ float fast_ex2(float x) {
    float y; asm("ex2.approx.f32 %0, %1;" : "=f"(y) : "f"(x)); return y;
}
__device__ __forceinline__ float fast_rcp(float x) {
    float y; asm("rcp.approx.f32 %0, %1;" : "=f"(y) : "f"(x)); return y;
}
// sigmoid(s) = 1 / (1 + 2^(-s*log2(e)))
__device__ __forceinline__ float fsigmoid(float s) {
    return fast_rcp(1.0f + fast_ex2(-1.44269504f * s));
}
// tanh(s) = 1 - 2/(exp(2s)+1); exp(2s) = 2^(2*log2(e)*s)
// Saturates correctly at +/-inf of the exp argument.
__device__ __forceinline__ float ftanh(float s) {
    float t = fast_ex2(2.88539008f * s);
    return fmaf(-2.0f, fast_rcp(t + 1.0f), 1.0f);
}

__device__ __forceinline__ void ffma2(u64& d, u64 a, u64 b, u64 c) {
    asm("fma.rn.f32x2 %0, %1, %2, %3;" : "=l"(d) : "l"(a), "l"(b), "l"(c));
}
__device__ __forceinline__ u64 add2(u64 a, u64 b) {
    u64 d; asm("add.rn.f32x2 %0, %1, %2;" : "=l"(d) : "l"(a), "l"(b)); return d;
}
__device__ __forceinline__ float2 unpk(u64 v) {
    float2 f; asm("mov.b64 {%0, %1}, %2;" : "=f"(f.x), "=f"(f.y) : "l"(v)); return f;
}

__global__ void __launch_bounds__(32, 14)
gru_kernel(const float* __restrict__ x,
           const float* __restrict__ w_ih,
           const float* __restrict__ w_hh,
           const float* __restrict__ b_ih,
           const float* __restrict__ b_hh,
           const float* __restrict__ head_w,
           const float* __restrict__ head_b,
           float* __restrict__ out,
           int B, int T)
{
    const int b = blockIdx.x;
    const int i = threadIdx.x;          // lane == hidden unit index, H == 32

    __shared__ __align__(16) float hsh[32];

    // Preload packed W_hh rows for this lane's unit: rows i (r), 32+i (z), 64+i (n).
    // Each row is 32 contiguous floats -> 16 packed f32x2 pairs.
    u64 wr2[16], wz2[16], wn2[16];
    {
        const u64* Wr = (const u64*)(w_hh + (0  + i) * 32);
        const u64* Wz = (const u64*)(w_hh + (32 + i) * 32);
        const u64* Wn = (const u64*)(w_hh + (64 + i) * 32);
        #pragma unroll
        for (int j = 0; j < 16; j++) { wr2[j] = Wr[j]; wz2[j] = Wz[j]; wn2[j] = Wn[j]; }
    }

    const float wir = w_ih[i], wiz = w_ih[32 + i], win = w_ih[64 + i];
    const float cr   = b_ih[i]      + b_hh[i];        // folded bias for r pre-activation
    const float cz   = b_ih[32 + i] + b_hh[32 + i];   // folded bias for z pre-activation
    const float cn_x = b_ih[64 + i];                  // x-side bias for n
    const float cn_h = b_hh[64 + i];                  // h-side bias for n (scaled by r)

    float h = 0.0f;
    const float* xb = x + (long long)b * T;

    for (int t0 = 0; t0 < T; t0 += 32) {
        float xq = xb[t0 + i];          // 32 timesteps, one per lane (coalesced)
        #pragma unroll 4
        for (int k = 0; k < 32; k++) {
            float xt = __shfl_sync(FULL_MASK, xq, k);

            __syncwarp();               // previous step's readers done
            hsh[i] = h;
            __syncwarp();               // h vector visible

            const u64* hp = (const u64*)hsh;   // 16 packed pairs, broadcast LDS.64
            u64 ar0 = 0, ar1 = 0, az0 = 0, az1 = 0, an0 = 0, an1 = 0;
            #pragma unroll
            for (int j = 0; j < 16; j += 2) {
                u64 h0 = hp[j], h1 = hp[j + 1];
                ffma2(ar0, wr2[j],     h0, ar0);
                ffma2(ar1, wr2[j + 1], h1, ar1);
                ffma2(az0, wz2[j],     h0, az0);
                ffma2(az1, wz2[j + 1], h1, az1);
                ffma2(an0, wn2[j],     h0, an0);
                ffma2(an1, wn2[j + 1], h1, an1);
            }
            float2 fr = unpk(add2(ar0, ar1));
            float2 fz = unpk(add2(az0, az1));
            float2 fn = unpk(add2(an0, an1));
            float hr = fr.x + fr.y;
            float hz = fz.x + fz.y;
            float hn = fn.x + fn.y + cn_h;

            float r = fsigmoid(fmaf(xt, wir, cr) + hr);
            float z = fsigmoid(fmaf(xt, wiz, cz) + hz);
            float n = ftanh(fmaf(r, hn, fmaf(xt, win, cn_x)));
            h = fmaf(z, h - n, n);      // (1-z)*n + z*h
        }
    }

    // Head: out[b][o] = sum_i h[i] * head_w[o][i] + head_b[o],  O = 2
    float p0 = h * head_w[i];
    float p1 = h * head_w[32 + i];
    #pragma unroll
    for (int m = 16; m > 0; m >>= 1) {
        p0 += __shfl_xor_sync(FULL_MASK, p0, m);
        p1 += __shfl_xor_sync(FULL_MASK, p1, m);
    }
    if (i == 0) {
        out[2 * b]     = p0 + head_b[0];
        out[2 * b + 1] = p1 + head_b[1];
    }
}

extern "C" void kernel_launch(void* const* d_in, const int* in_sizes, int n_in,
                              void* d_out, int out_size) {
    const float* x      = (const float*)d_in[0];
    const float* w_ih   = (const float*)d_in[1];
    const float* w_hh   = (const float*)d_in[2];
    const float* b_ih   = (const float*)d_in[3];
    const float* b_hh   = (const float*)d_in[4];
    const float* head_w = (const float*)d_in[5];
    const float* head_b = (const float*)d_in[6];
    float* out = (float*)d_out;

    const int B = out_size / 2;           // 2048
    const int T = in_sizes[0] / B;        // 2048

    gru_kernel<<<B, 32>>>(x, w_ih, w_hh, b_ih, b_hh, head_w, head_b, out, B, T);
}

// round 2
// speedup vs baseline: 1.0001x; 1.0001x over previous
#include <cuda_runtime.h>

// SimpleGRU: B=2048 sequences, T=2048 steps, H=32, scalar input.
// One warp per batch element; lane i owns hidden unit i and holds the
// three W_hh rows (r,z,n) for unit i as packed f32x2 pairs in registers.
// Per-step matvec = 48 fma.rn.f32x2. h broadcast via 128B shared buffer.

#define FULL_MASK 0xffffffffu

using u64 = unsigned long long;

__device__ __forceinline__ float fast_ex2(float x) {
    float y; asm("ex2.approx.f32 %0, %1;" : "=f"(y) : "f"(x)); return y;
}
__device__ __forceinline__ float fast_rcp(float x) {
    float y; asm("rcp.approx.f32 %0, %1;" : "=f"(y) : "f"(x)); return y;
}
// sigmoid(s) = 1 / (1 + 2^(-s*log2(e)))
__device__ __forceinline__ float fsigmoid(float s) {
    return fast_rcp(1.0f + fast_ex2(-1.44269504f * s));
}
// tanh(s) = 1 - 2/(exp(2s)+1); exp(2s) = 2^(2*log2(e)*s)
// Saturates correctly at +/-inf of the exp argument.
__device__ __forceinline__ float ftanh(float s) {
    float t = fast_ex2(2.88539008f * s);
    return fmaf(-2.0f, fast_rcp(t + 1.0f), 1.0f);
}

__device__ __forceinline__ void ffma2(u64& d, u64 a, u64 b, u64 c) {
    asm("fma.rn.f32x2 %0, %1, %2, %3;" : "=l"(d) : "l"(a), "l"(b), "l"(c));
}
__device__ __forceinline__ u64 add2(u64 a, u64 b) {
    u64 d; asm("add.rn.f32x2 %0, %1, %2;" : "=l"(d) : "l"(a), "l"(b)); return d;
}
__device__ __forceinline__ float2 unpk(u64 v) {
    float2 f; asm("mov.b64 {%0, %1}, %2;" : "=f"(f.x), "=f"(f.y) : "l"(v)); return f;
}

__global__ void __launch_bounds__(32, 14)
gru_kernel(const float* __restrict__ x,
           const float* __restrict__ w_ih,
           const float* __restrict__ w_hh,
           const float* __restrict__ b_ih,
           const float* __restrict__ b_hh,
           const float* __restrict__ head_w,
           const float* __restrict__ head_b,
           float* __restrict__ out,
           int B, int T)
{
    const int b = blockIdx.x;
    const int i = threadIdx.x;          // lane == hidden unit index, H == 32

    __shared__ __align__(16) float hsh[32];

    // Preload packed W_hh rows for this lane's unit: rows i (r), 32+i (z), 64+i (n).
    // Each row is 32 contiguous floats -> 16 packed f32x2 pairs.
    u64 wr2[16], wz2[16], wn2[16];
    {
        const u64* Wr = (const u64*)(w_hh + (0  + i) * 32);
        const u64* Wz = (const u64*)(w_hh + (32 + i) * 32);
        const u64* Wn = (const u64*)(w_hh + (64 + i) * 32);
        #pragma unroll
        for (int j = 0; j < 16; j++) { wr2[j] = Wr[j]; wz2[j] = Wz[j]; wn2[j] = Wn[j]; }
    }

    const float wir = w_ih[i], wiz = w_ih[32 + i], win = w_ih[64 + i];
    const float cr   = b_ih[i]      + b_hh[i];        // folded bias for r pre-activation
    const float cz   = b_ih[32 + i] + b_hh[32 + i];   // folded bias for z pre-activation
    const float cn_x = b_ih[64 + i];                  // x-side bias for n
    const float cn_h = b_hh[64 + i];                  // h-side bias for n (scaled by r)

    float h = 0.0f;
    const float* xb = x + (long long)b * T;

    for (int t0 = 0; t0 < T; t0 += 32) {
        float xq = xb[t0 + i];          // 32 timesteps, one per lane (coalesced)
        #pragma unroll 4
        for (int k = 0; k < 32; k++) {
            float xt = __shfl_sync(FULL_MASK, xq, k);

            __syncwarp();               // previous step's readers done
            hsh[i] = h;
            __syncwarp();               // h vector visible

            const u64* hp = (const u64*)hsh;   // 16 packed pairs, broadcast LDS.64
            u64 ar0 = 0, ar1 = 0, az0 = 0, az1 = 0, an0 = 0, an1 = 0;
            #pragma unroll
            for (int j = 0; j < 16; j += 2) {
                u64 h0 = hp[j], h1 = hp[j + 1];
                ffma2(ar0, wr2[j],     h0, ar0);
                ffma2(ar1, wr2[j + 1], h1, ar1);
                ffma2(az0, wz2[j],     h0, az0);
                ffma2(az1, wz2[j + 1], h1, az1);
                ffma2(an0, wn2[j],     h0, an0);
                ffma2(an1, wn2[j + 1], h1, an1);
            }
            float2 fr = unpk(add2(ar0, ar1));
            float2 fz = unpk(add2(az0, az1));
            float2 fn = unpk(add2(an0, an1));
            float hr = fr.x + fr.y;
            float hz = fz.x + fz.y;
            float hn = fn.x + fn.y + cn_h;

            float r = fsigmoid(fmaf(xt, wir, cr) + hr);
            float z = fsigmoid(fmaf(xt, wiz, cz) + hz);
            float n = ftanh(fmaf(r, hn, fmaf(xt, win, cn_x)));
            h = fmaf(z, h - n, n);      // (1-z)*n + z*h
        }
    }

    // Head: out[b][o] = sum_i h[i] * head_w[o][i] + head_b[o],  O = 2
    float p0 = h * head_w[i];
    float p1 = h * head_w[32 + i];
    #pragma unroll
    for (int m = 16; m > 0; m >>= 1) {
        p0 += __shfl_xor_sync(FULL_MASK, p0, m);
        p1 += __shfl_xor_sync(FULL_MASK, p1, m);
    }
    if (i == 0) {
        out[2 * b]     = p0 + head_b[0];
        out[2 * b + 1] = p1 + head_b[1];
    }
}

extern "C" void kernel_launch(void* const* d_in, const int* in_sizes, int n_in,
                              void* d_out, int out_size) {
    const float* x      = (const float*)d_in[0];
    const float* w_ih   = (const float*)d_in[1];
    const float* w_hh   = (const float*)d_in[2];
    const float* b_ih   = (const float*)d_in[3];
    const float* b_hh   = (const float*)d_in[4];
    const float* head_w = (const float*)d_in[5];
    const float* head_b = (const float*)d_in[6];
    float* out = (float*)d_out;

    const int B = out_size / 2;           // 2048
    const int T = in_sizes[0] / B;        // 2048

    gru_kernel<<<B, 32>>>(x, w_ih, w_hh, b_ih, b_hh, head_w, head_b, out, B, T);
}